// round 14
// baseline (speedup 1.0000x reference)
#include <cuda_runtime.h>

// Problem constants
#define BB 2
#define SS 2048
#define DM 1024
#define NH 16
#define DK 64
#define MTOT (BB*SS)      // 4096
#define NHD  (NH*DK)      // 1024
#define LOG2E 1.44269504088896f

// Scratch (allocation-free static device globals). u32 = tf32 bit payloads.
__device__ unsigned g_xq[MTOT*DM];     // prepped activations [row][k perm8]
__device__ unsigned g_xk[MTOT*DM];
__device__ unsigned g_xv[MTOT*DM];
__device__ unsigned g_wq[DM*NHD];      // prepped weights [k/8][n][perm8 over k]
__device__ unsigned g_wk[DM*NHD];
__device__ unsigned g_wv[DM*NHD];
__device__ unsigned g_wo[NHD*DM];
__device__ unsigned g_q[BB*NH*SS*DK];  // [b,h][s][d perm8], scaled 0.125*log2e
__device__ unsigned g_k[BB*NH*SS*DK];  // [b,h][s][d perm8]
__device__ unsigned g_v[BB*NH*DK*SS];  // [b,h][d][s perm8]  (transposed)
__device__ unsigned g_ctx[MTOT*NHD];   // [row][c perm8]
__device__ float    g_maskl[BB*SS];    // mask * log2e

// ---------------------------------------------------------------------------
// helpers
// ---------------------------------------------------------------------------
__device__ __forceinline__ unsigned f2tf(float x) {
    unsigned u; asm("cvt.rna.tf32.f32 %0, %1;" : "=r"(u) : "f"(x)); return u;
}
__device__ __forceinline__ float fex2(float x) {
    float y; asm("ex2.approx.ftz.f32 %0, %1;" : "=f"(y) : "f"(x)); return y;
}
__device__ __forceinline__ void mma8(float* c, const unsigned* a, unsigned b0, unsigned b1) {
    asm volatile(
        "mma.sync.aligned.m16n8k8.row.col.f32.tf32.tf32.f32 "
        "{%0,%1,%2,%3}, {%4,%5,%6,%7}, {%8,%9}, {%0,%1,%2,%3};\n"
        : "+f"(c[0]), "+f"(c[1]), "+f"(c[2]), "+f"(c[3])
        : "r"(a[0]), "r"(a[1]), "r"(a[2]), "r"(a[3]), "r"(b0), "r"(b1));
}
__device__ __forceinline__ void cpa16(void* dst, const void* src) {
    unsigned d = (unsigned)__cvta_generic_to_shared(dst);
    asm volatile("cp.async.cg.shared.global [%0], [%1], 16;\n" :: "r"(d), "l"(src));
}
__device__ __forceinline__ void cp_commit() { asm volatile("cp.async.commit_group;\n"); }
template <int N>
__device__ __forceinline__ void cp_wait() { asm volatile("cp.async.wait_group %0;\n" :: "n"(N)); }

// element j of an 8-group stored at pos8(j); order {0,4,1,5,2,6,3,7}
// => uint2 at position 2*t4 yields elements (t4, t4+4): one LDS.64 per mma pair.
__device__ __forceinline__ int pos8(int j) { return (j & 3) * 2 + (j >> 2); }

// ---------------------------------------------------------------------------
// prep kernels (merged)
// ---------------------------------------------------------------------------
__global__ void __launch_bounds__(256) prep_x3(const float* __restrict__ Xq,
                                               const float* __restrict__ Xk,
                                               const float* __restrict__ Xv,
                                               unsigned* __restrict__ Pq,
                                               unsigned* __restrict__ Pk,
                                               unsigned* __restrict__ Pv)
{
    const int z = blockIdx.y;
    const float* X = (z == 0) ? Xq : (z == 1) ? Xk : Xv;
    unsigned* Xp   = (z == 0) ? Pq : (z == 1) ? Pk : Pv;
    int id = blockIdx.x * 256 + threadIdx.x;            // 524288 groups of 8
    const float4 lo = *(const float4*)(X + (size_t)id * 8);
    const float4 hi = *(const float4*)(X + (size_t)id * 8 + 4);
    uint4 o0 = make_uint4(f2tf(lo.x), f2tf(hi.x), f2tf(lo.y), f2tf(hi.y));
    uint4 o1 = make_uint4(f2tf(lo.z), f2tf(hi.z), f2tf(lo.w), f2tf(hi.w));
    *(uint4*)(Xp + (size_t)id * 8)     = o0;
    *(uint4*)(Xp + (size_t)id * 8 + 4) = o1;
}

// W fp32 [1024 k][1024 n] -> Wp[k/8][n][perm8 across k]; z selects which W.
__global__ void __launch_bounds__(256) prep_w4(const float* __restrict__ Wq,
                                               const float* __restrict__ Wk,
                                               const float* __restrict__ Wv,
                                               const float* __restrict__ Wo,
                                               unsigned* __restrict__ Pq,
                                               unsigned* __restrict__ Pk,
                                               unsigned* __restrict__ Pv,
                                               unsigned* __restrict__ Po)
{
    const int z = blockIdx.y;
    const float* W = (z == 0) ? Wq : (z == 1) ? Wk : (z == 2) ? Wv : Wo;
    unsigned* Wp   = (z == 0) ? Pq : (z == 1) ? Pk : (z == 2) ? Pv : Po;
    int id = blockIdx.x * 256 + threadIdx.x;            // 131072 = 128a * 1024n
    int a = id >> 10, n = id & 1023;
    float r[8];
    #pragma unroll
    for (int j = 0; j < 8; j++) r[j] = W[(size_t)(8 * a + j) * NHD + n];
    uint4 o0 = make_uint4(f2tf(r[0]), f2tf(r[4]), f2tf(r[1]), f2tf(r[5]));
    uint4 o1 = make_uint4(f2tf(r[2]), f2tf(r[6]), f2tf(r[3]), f2tf(r[7]));
    *(uint4*)(Wp + (size_t)a * (NHD * 8) + n * 8)     = o0;
    *(uint4*)(Wp + (size_t)a * (NHD * 8) + n * 8 + 4) = o1;
}

__global__ void __launch_bounds__(256) prep_mask(const float* __restrict__ m,
                                                 float* __restrict__ out)
{
    int id = blockIdx.x * 256 + threadIdx.x;            // 4096
    out[id] = m[id] * LOG2E;
}

// ---------------------------------------------------------------------------
// GEMM core: 128x128 tile, BK=16, 256 thr (8 warps 2x4). All operands u32 tf32.
// As[2][128*24] (16 data + 8 pad per row), Bs[2][2*128*8]. No cvt, LDS.64 frags.
// ---------------------------------------------------------------------------
__device__ __forceinline__ void gemm_core(const unsigned* __restrict__ A,
                                          const unsigned* __restrict__ Wp,
                                          unsigned* smA, unsigned* smB,
                                          float acc[4][4][4],
                                          int rowBase, int colBase)
{
    const int tid  = threadIdx.x;
    const int wid  = tid >> 5;
    const int lane = tid & 31;
    const int g    = lane >> 2;
    const int t4   = lane & 3;
    const int wm   = wid >> 2;
    const int wn   = wid & 3;

    #pragma unroll
    for (int mt = 0; mt < 4; mt++)
        #pragma unroll
        for (int nt = 0; nt < 4; nt++)
            #pragma unroll
            for (int i = 0; i < 4; i++) acc[mt][nt][i] = 0.f;

    auto loadT = [&](int k0, int bufi) {
        unsigned* Ad = smA + bufi * 3072;
        unsigned* Bd = smB + bufi * 2048;
        #pragma unroll
        for (int j = 0; j < 2; j++) {
            int c = tid + j * 256;                      // 0..511
            int ra = c >> 2, ch = c & 3;
            cpa16(&Ad[ra * 24 + ch * 4],
                  A + (size_t)(rowBase + ra) * DM + k0 + ch * 4);
            int ksl = c >> 8, rem = c & 255;
            int rb = rem >> 1, hc = rem & 1;
            cpa16(&Bd[ksl * 1024 + rb * 8 + hc * 4],
                  Wp + (size_t)((k0 >> 3) + ksl) * (NHD * 8) + (colBase + rb) * 8 + hc * 4);
        }
    };

    loadT(0, 0); cp_commit();
    int buf = 0;

    for (int k0 = 0; k0 < DM; k0 += 16) {
        if (k0 + 16 < DM) { loadT(k0 + 16, buf ^ 1); cp_commit(); cp_wait<1>(); }
        else              { cp_wait<0>(); }
        __syncthreads();

        const unsigned* Ad = smA + buf * 3072;
        const unsigned* Bd = smB + buf * 2048;

        #pragma unroll
        for (int ks = 0; ks < 2; ks++) {
            unsigned af[4][4], bf[4][2];
            #pragma unroll
            for (int mt = 0; mt < 4; mt++) {
                const int row = wm * 64 + mt * 16 + g;
                uint2 a01 = *(const uint2*)&Ad[row * 24 + ks * 8 + 2 * t4];
                uint2 a23 = *(const uint2*)&Ad[(row + 8) * 24 + ks * 8 + 2 * t4];
                af[mt][0] = a01.x; af[mt][1] = a23.x; af[mt][2] = a01.y; af[mt][3] = a23.y;
            }
            #pragma unroll
            for (int nt = 0; nt < 4; nt++) {
                uint2 bb = *(const uint2*)&Bd[ks * 1024 + (wn * 32 + nt * 8 + g) * 8 + 2 * t4];
                bf[nt][0] = bb.x; bf[nt][1] = bb.y;
            }
            #pragma unroll
            for (int mt = 0; mt < 4; mt++)
                #pragma unroll
                for (int nt = 0; nt < 4; nt++)
                    mma8(acc[mt][nt], af[mt], bf[nt][0], bf[nt][1]);
        }
        __syncthreads();
        buf ^= 1;
    }
}

// merged QKV projection: grid.z = 0(Q)/1(K)/2(V)
__global__ void __launch_bounds__(256) qkv_gemm(
    const unsigned* __restrict__ xq, const unsigned* __restrict__ xk,
    const unsigned* __restrict__ xv, const unsigned* __restrict__ wq,
    const unsigned* __restrict__ wk, const unsigned* __restrict__ wv,
    unsigned* __restrict__ oq, unsigned* __restrict__ ok, unsigned* __restrict__ ov)
{
    __shared__ unsigned smA[2 * 3072];
    __shared__ unsigned smB[2 * 2048];
    const int z = blockIdx.z;
    const unsigned* A  = (z == 0) ? xq : (z == 1) ? xk : xv;
    const unsigned* Wp = (z == 0) ? wq : (z == 1) ? wk : wv;

    const int rowBase = blockIdx.y * 128;
    const int colBase = blockIdx.x * 128;
    float acc[4][4][4];
    gemm_core(A, Wp, smA, smB, acc, rowBase, colBase);

    const int tid = threadIdx.x, wid = tid >> 5, lane = tid & 31;
    const int g = lane >> 2, t4 = lane & 3, wm = wid >> 2, wn = wid & 3;
    const int pA = pos8(2 * t4), pB = pos8(2 * t4 + 1);

    if (z < 2) {   // Q or K: [b,h][s][d perm8]
        unsigned* O = z ? ok : oq;
        const float sc = z ? 1.f : 0.125f * LOG2E;
        #pragma unroll
        for (int mt = 0; mt < 4; mt++) {
            const int r0 = rowBase + wm * 64 + mt * 16 + g;
            const int bI = r0 >> 11, sI = r0 & 2047;
            #pragma unroll
            for (int nt = 0; nt < 4; nt++) {
                const int c0 = colBase + wn * 32 + nt * 8 + 2 * t4;
                const int hI = c0 >> 6, dg = (c0 & 63) & ~7;
                size_t b0 = ((size_t)(bI * NH + hI) * SS + sI) * DK + dg;
                size_t b1 = b0 + 8 * DK;
                O[b0 + pA] = f2tf(acc[mt][nt][0] * sc);
                O[b0 + pB] = f2tf(acc[mt][nt][1] * sc);
                O[b1 + pA] = f2tf(acc[mt][nt][2] * sc);
                O[b1 + pB] = f2tf(acc[mt][nt][3] * sc);
            }
        }
    } else {       // V transposed: [b,h][d][s perm8]
        const int pG = pos8(g);
        #pragma unroll
        for (int mt = 0; mt < 4; mt++) {
            const int r0 = rowBase + wm * 64 + mt * 16 + g;
            const int bI = r0 >> 11, sI = r0 & 2047;
            const int sp = (sI & ~7) + pG;
            #pragma unroll
            for (int nt = 0; nt < 4; nt++) {
                const int c0 = colBase + wn * 32 + nt * 8 + 2 * t4;
                const int hI = c0 >> 6, dI = c0 & 63;
                size_t base = ((size_t)(bI * NH + hI) * DK + dI) * SS;
                ov[base + sp]          = f2tf(acc[mt][nt][0]);
                ov[base + SS + sp]     = f2tf(acc[mt][nt][1]);
                ov[base + sp + 8]      = f2tf(acc[mt][nt][2]);
                ov[base + SS + sp + 8] = f2tf(acc[mt][nt][3]);
            }
        }
    }
}

__global__ void __launch_bounds__(256) out_gemm(const unsigned* __restrict__ ctx,
                                                const unsigned* __restrict__ wo,
                                                float* __restrict__ C)
{
    __shared__ unsigned smA[2 * 3072];
    __shared__ unsigned smB[2 * 2048];
    const int rowBase = blockIdx.y * 128;
    const int colBase = blockIdx.x * 128;
    float acc[4][4][4];
    gemm_core(ctx, wo, smA, smB, acc, rowBase, colBase);

    const int tid = threadIdx.x, wid = tid >> 5, lane = tid & 31;
    const int g = lane >> 2, t4 = lane & 3, wm = wid >> 2, wn = wid & 3;
    #pragma unroll
    for (int mt = 0; mt < 4; mt++) {
        const int r0 = rowBase + wm * 64 + mt * 16 + g;
        #pragma unroll
        for (int nt = 0; nt < 4; nt++) {
            const int c0 = colBase + wn * 32 + nt * 8 + 2 * t4;
            *(float2*)&C[(size_t)r0 * NHD + c0]       = make_float2(acc[mt][nt][0], acc[mt][nt][1]);
            *(float2*)&C[(size_t)(r0 + 8) * NHD + c0] = make_float2(acc[mt][nt][2], acc[mt][nt][3]);
        }
    }
}

// ---------------------------------------------------------------------------
// Tensor-core flash attention v3: 256 threads = 8 warps over 128 q-rows.
// Per KV tile of 64: warp w computes rows [16w,16w+16). No cvt in loop (except
// 32 P-stores), LDS.64 fragments, no max tracking, log2e folded, mask in smem.
// smem u32: Ks[2][64*72] | Vt[2][64*72] | Ps[128*72] | ms[2048] = 118784 B
// ---------------------------------------------------------------------------
__global__ void __launch_bounds__(256) attn_tc3(const unsigned* __restrict__ q,
                                                const unsigned* __restrict__ k,
                                                const unsigned* __restrict__ v,
                                                const float* __restrict__ maskl,
                                                unsigned* __restrict__ ctx)
{
    extern __shared__ unsigned sm[];
    unsigned* Ks0 = sm;                 // 2 * 4608
    unsigned* Vs0 = sm + 9216;          // 2 * 4608
    unsigned* Ps  = sm + 18432;         // 128*72 = 9216
    float*    ms  = (float*)(sm + 27648);  // 2048

    const int tid  = threadIdx.x;
    const int wid  = tid >> 5;
    const int lane = tid & 31;
    const int g    = lane >> 2;
    const int t4   = lane & 3;
    const int m0   = wid * 16;
    const int pA   = pos8(2 * t4), pB = pos8(2 * t4 + 1);

    const int bh = blockIdx.z * NH + blockIdx.y;
    const int q0 = blockIdx.x * 128;
    const unsigned* kb = k + (size_t)bh * SS * DK;
    const unsigned* vb = v + (size_t)bh * DK * SS;

    auto loadKV = [&](int kv0, int bufi) {
        unsigned* Kd = Ks0 + bufi * 4608;
        unsigned* Vd = Vs0 + bufi * 4608;
        #pragma unroll
        for (int j = 0; j < 4; j++) {
            int idx = tid + j * 256;          // 0..1023
            int r = idx >> 4, c = idx & 15;   // row, 16B chunk
            cpa16(&Kd[r * 72 + c * 4], kb + (size_t)(kv0 + r) * DK + c * 4);
            cpa16(&Vd[r * 72 + c * 4], vb + (size_t)r * SS + kv0 + c * 4);
        }
    };

    loadKV(0, 0); cp_commit();

    // mask (pre-scaled by log2e) -> smem
    {
        const float* mrow = maskl + (size_t)blockIdx.z * SS;
        #pragma unroll
        for (int j = 0; j < 8; j++) ms[tid + j * 256] = mrow[tid + j * 256];
    }

    // Q fragments straight from gmem (prepped: tf32 bits, 0.125*log2e folded)
    unsigned qa[8][4];
    const unsigned* qp = q + ((size_t)bh * SS + q0 + m0 + g) * DK;
    #pragma unroll
    for (int ks = 0; ks < 8; ks++) {
        uint2 u0 = *(const uint2*)(qp + ks * 8 + 2 * t4);
        uint2 u1 = *(const uint2*)(qp + 8 * DK + ks * 8 + 2 * t4);
        qa[ks][0] = u0.x; qa[ks][1] = u1.x; qa[ks][2] = u0.y; qa[ks][3] = u1.y;
    }

    float o[8][4];
    #pragma unroll
    for (int nt = 0; nt < 8; nt++)
        #pragma unroll
        for (int i = 0; i < 4; i++) o[nt][i] = 0.f;
    float l0 = 0.f, l1 = 0.f;

    int buf = 0;

    for (int it = 0; it < SS / 64; it++) {
        const int kv0 = it * 64;
        if (it + 1 < SS / 64) { loadKV(kv0 + 64, buf ^ 1); cp_commit(); cp_wait<1>(); }
        else                  { cp_wait<0>(); }
        __syncthreads();

        const unsigned* Ks = Ks0 + buf * 4608;
        const unsigned* Vs = Vs0 + buf * 4608;

        // ---- scores (log2e-scaled): S = Q @ K^T ----
        float s[8][4];
        #pragma unroll
        for (int nt = 0; nt < 8; nt++)
            #pragma unroll
            for (int i = 0; i < 4; i++) s[nt][i] = 0.f;

        #pragma unroll
        for (int ks = 0; ks < 8; ks++) {
            #pragma unroll
            for (int nt = 0; nt < 8; nt++) {
                uint2 kk2 = *(const uint2*)&Ks[(nt * 8 + g) * 72 + ks * 8 + 2 * t4];
                mma8(s[nt], qa[ks], kk2.x, kk2.y);
            }
        }

        // ---- p = 2^(s + mask*log2e); row sums; P -> smem ----
        #pragma unroll
        for (int nt = 0; nt < 8; nt++) {
            const int c = nt * 8 + 2 * t4;
            const float mk0 = ms[kv0 + c];
            const float mk1 = ms[kv0 + c + 1];
            float p0 = fex2(s[nt][0] + mk0);
            float p1 = fex2(s[nt][1] + mk1);
            float p2 = fex2(s[nt][2] + mk0);
            float p3 = fex2(s[nt][3] + mk1);
            l0 += p0 + p1;
            l1 += p2 + p3;
            const int base = (m0 + g) * 72 + nt * 8;
            Ps[base + pA]          = f2tf(p0);
            Ps[base + pB]          = f2tf(p1);
            Ps[base + 8 * 72 + pA] = f2tf(p2);
            Ps[base + 8 * 72 + pB] = f2tf(p3);
        }
        __syncwarp();   // P rows are private to this warp

        // ---- O += P @ V ----
        #pragma unroll
        for (int ks = 0; ks < 8; ks++) {
            uint2 pa01 = *(const uint2*)&Ps[(m0 + g) * 72 + ks * 8 + 2 * t4];
            uint2 pa23 = *(const uint2*)&Ps[(m0 + 8 + g) * 72 + ks * 8 + 2 * t4];
            unsigned pa[4] = { pa01.x, pa23.x, pa01.y, pa23.y };
            #pragma unroll
            for (int nt = 0; nt < 8; nt++) {
                uint2 vv = *(const uint2*)&Vs[(nt * 8 + g) * 72 + ks * 8 + 2 * t4];
                mma8(o[nt], pa, vv.x, vv.y);
            }
        }
        __syncthreads();   // everyone done with buf before refill
        buf ^= 1;
    }

    // ---- deferred row-sum reduction + normalize + write prepped ctx ----
    l0 += __shfl_xor_sync(0xffffffffu, l0, 1);
    l0 += __shfl_xor_sync(0xffffffffu, l0, 2);
    l1 += __shfl_xor_sync(0xffffffffu, l1, 1);
    l1 += __shfl_xor_sync(0xffffffffu, l1, 2);
    const float inv0 = 1.f / l0;
    const float inv1 = 1.f / l1;

    const int row0 = q0 + m0 + g;
    const size_t ob = ((size_t)blockIdx.z * SS + row0) * NHD + blockIdx.y * DK;
    #pragma unroll
    for (int nt = 0; nt < 8; nt++) {
        const size_t cb = ob + nt * 8;
        ctx[cb + pA]           = f2tf(o[nt][0] * inv0);
        ctx[cb + pB]           = f2tf(o[nt][1] * inv0);
        ctx[cb + 8 * NHD + pA] = f2tf(o[nt][2] * inv1);
        ctx[cb + 8 * NHD + pB] = f2tf(o[nt][3] * inv1);
    }
}

// ---------------------------------------------------------------------------
// Launch
// ---------------------------------------------------------------------------
extern "C" void kernel_launch(void* const* d_in, const int* in_sizes, int n_in,
                              void* d_out, int out_size)
{
    (void)in_sizes; (void)n_in; (void)out_size;
    const float* query = (const float*)d_in[0];
    const float* key   = (const float*)d_in[1];
    const float* value = (const float*)d_in[2];
    const float* mask  = (const float*)d_in[3];
    const float* Wq    = (const float*)d_in[4];
    const float* Wk    = (const float*)d_in[5];
    const float* Wv    = (const float*)d_in[6];
    const float* Wo    = (const float*)d_in[7];
    float* out = (float*)d_out;

    unsigned *xq, *xk, *xv, *wq, *wk, *wv, *wo, *qd, *kd, *vd, *ctx;
    float* ml;
    cudaGetSymbolAddress((void**)&xq,  g_xq);
    cudaGetSymbolAddress((void**)&xk,  g_xk);
    cudaGetSymbolAddress((void**)&xv,  g_xv);
    cudaGetSymbolAddress((void**)&wq,  g_wq);
    cudaGetSymbolAddress((void**)&wk,  g_wk);
    cudaGetSymbolAddress((void**)&wv,  g_wv);
    cudaGetSymbolAddress((void**)&wo,  g_wo);
    cudaGetSymbolAddress((void**)&qd,  g_q);
    cudaGetSymbolAddress((void**)&kd,  g_k);
    cudaGetSymbolAddress((void**)&vd,  g_v);
    cudaGetSymbolAddress((void**)&ctx, g_ctx);
    cudaGetSymbolAddress((void**)&ml,  g_maskl);

    // preps (merged)
    prep_x3<<<dim3(2048, 3), 256>>>(query, key, value, xq, xk, xv);
    prep_w4<<<dim3(512, 4), 256>>>(Wq, Wk, Wv, Wo, wq, wk, wv, wo);
    prep_mask<<<16, 256>>>(mask, ml);

    // merged QKV projection
    dim3 qgrid(NHD / 128, MTOT / 128, 3);   // (8, 32, 3)
    qkv_gemm<<<qgrid, 256>>>(xq, xk, xv, wq, wk, wv, qd, kd, vd);

    // attention: 512 blocks x 256 threads, 118784 B dynamic smem
    const int attn_smem = (27648 + 2048) * 4;
    static int smem_set = 0;
    if (!smem_set) {
        cudaFuncSetAttribute(attn_tc3, cudaFuncAttributeMaxDynamicSharedMemorySize, attn_smem);
        smem_set = 1;
    }
    dim3 agrid(SS / 128, NH, BB);           // (16, 16, 2)
    attn_tc3<<<agrid, 256, attn_smem>>>(qd, kd, vd, ml, ctx);

    // output projection
    dim3 ogrid(NHD / 128, MTOT / 128);      // (8, 32)
    out_gemm<<<ogrid, 256>>>(ctx, wo, out);
}

// round 15
// speedup vs baseline: 1.4931x; 1.4931x over previous
#include <cuda_runtime.h>

// Problem constants
#define BB 2
#define SS 2048
#define DM 1024
#define NH 16
#define DK 64
#define MTOT (BB*SS)      // 4096
#define NHD  (NH*DK)      // 1024
#define LOG2E 1.44269504088896f

// Scratch (allocation-free static device globals). u32 = tf32 bit payloads.
__device__ unsigned g_xq[MTOT*DM];     // prepped activations [row][k perm8]
__device__ unsigned g_xk[MTOT*DM];
__device__ unsigned g_xv[MTOT*DM];
__device__ unsigned g_wq[DM*NHD];      // prepped weights [k/8][n][perm8 over k]
__device__ unsigned g_wk[DM*NHD];
__device__ unsigned g_wv[DM*NHD];
__device__ unsigned g_wo[NHD*DM];
__device__ unsigned g_q[BB*NH*SS*DK];  // [b,h][s][d perm8], scaled 0.125*log2e
__device__ unsigned g_k[BB*NH*SS*DK];  // [b,h][s][d perm8]
__device__ unsigned g_v[BB*NH*DK*SS];  // [b,h][d][s perm8]  (transposed)
__device__ unsigned g_ctx[MTOT*NHD];   // [row][c perm8]
__device__ float    g_maskl[BB*SS];    // mask * log2e

// ---------------------------------------------------------------------------
// helpers
// ---------------------------------------------------------------------------
__device__ __forceinline__ unsigned f2tf(float x) {
    unsigned u; asm("cvt.rna.tf32.f32 %0, %1;" : "=r"(u) : "f"(x)); return u;
}
__device__ __forceinline__ float fex2(float x) {
    float y; asm("ex2.approx.ftz.f32 %0, %1;" : "=f"(y) : "f"(x)); return y;
}
__device__ __forceinline__ void mma8(float* c, const unsigned* a, unsigned b0, unsigned b1) {
    asm volatile(
        "mma.sync.aligned.m16n8k8.row.col.f32.tf32.tf32.f32 "
        "{%0,%1,%2,%3}, {%4,%5,%6,%7}, {%8,%9}, {%0,%1,%2,%3};\n"
        : "+f"(c[0]), "+f"(c[1]), "+f"(c[2]), "+f"(c[3])
        : "r"(a[0]), "r"(a[1]), "r"(a[2]), "r"(a[3]), "r"(b0), "r"(b1));
}
__device__ __forceinline__ void cpa16(void* dst, const void* src) {
    unsigned d = (unsigned)__cvta_generic_to_shared(dst);
    asm volatile("cp.async.cg.shared.global [%0], [%1], 16;\n" :: "r"(d), "l"(src));
}
__device__ __forceinline__ void cp_commit() { asm volatile("cp.async.commit_group;\n"); }
template <int N>
__device__ __forceinline__ void cp_wait() { asm volatile("cp.async.wait_group %0;\n" :: "n"(N)); }

// element j of an 8-group stored at pos8(j); order {0,4,1,5,2,6,3,7}
// => uint2 at position 2*t4 yields elements (t4, t4+4): one LDS.64 per mma pair.
__device__ __forceinline__ int pos8(int j) { return (j & 3) * 2 + (j >> 2); }

// ---------------------------------------------------------------------------
// prep kernels (merged)
// ---------------------------------------------------------------------------
__global__ void __launch_bounds__(256) prep_x3(const float* __restrict__ Xq,
                                               const float* __restrict__ Xk,
                                               const float* __restrict__ Xv,
                                               unsigned* __restrict__ Pq,
                                               unsigned* __restrict__ Pk,
                                               unsigned* __restrict__ Pv)
{
    const int z = blockIdx.y;
    const float* X = (z == 0) ? Xq : (z == 1) ? Xk : Xv;
    unsigned* Xp   = (z == 0) ? Pq : (z == 1) ? Pk : Pv;
    int id = blockIdx.x * 256 + threadIdx.x;            // 524288 groups of 8
    const float4 lo = *(const float4*)(X + (size_t)id * 8);
    const float4 hi = *(const float4*)(X + (size_t)id * 8 + 4);
    uint4 o0 = make_uint4(f2tf(lo.x), f2tf(hi.x), f2tf(lo.y), f2tf(hi.y));
    uint4 o1 = make_uint4(f2tf(lo.z), f2tf(hi.z), f2tf(lo.w), f2tf(hi.w));
    *(uint4*)(Xp + (size_t)id * 8)     = o0;
    *(uint4*)(Xp + (size_t)id * 8 + 4) = o1;
}

// W fp32 [1024 k][1024 n] -> Wp[k/8][n][perm8 across k]; z selects which W.
__global__ void __launch_bounds__(256) prep_w4(const float* __restrict__ Wq,
                                               const float* __restrict__ Wk,
                                               const float* __restrict__ Wv,
                                               const float* __restrict__ Wo,
                                               unsigned* __restrict__ Pq,
                                               unsigned* __restrict__ Pk,
                                               unsigned* __restrict__ Pv,
                                               unsigned* __restrict__ Po)
{
    const int z = blockIdx.y;
    const float* W = (z == 0) ? Wq : (z == 1) ? Wk : (z == 2) ? Wv : Wo;
    unsigned* Wp   = (z == 0) ? Pq : (z == 1) ? Pk : (z == 2) ? Pv : Po;
    int id = blockIdx.x * 256 + threadIdx.x;            // 131072 = 128a * 1024n
    int a = id >> 10, n = id & 1023;
    float r[8];
    #pragma unroll
    for (int j = 0; j < 8; j++) r[j] = W[(size_t)(8 * a + j) * NHD + n];
    uint4 o0 = make_uint4(f2tf(r[0]), f2tf(r[4]), f2tf(r[1]), f2tf(r[5]));
    uint4 o1 = make_uint4(f2tf(r[2]), f2tf(r[6]), f2tf(r[3]), f2tf(r[7]));
    *(uint4*)(Wp + (size_t)a * (NHD * 8) + n * 8)     = o0;
    *(uint4*)(Wp + (size_t)a * (NHD * 8) + n * 8 + 4) = o1;
}

__global__ void __launch_bounds__(256) prep_mask(const float* __restrict__ m,
                                                 float* __restrict__ out)
{
    int id = blockIdx.x * 256 + threadIdx.x;            // 4096
    out[id] = m[id] * LOG2E;
}

// ---------------------------------------------------------------------------
// GEMM core: 128x128 tile, BK=16, 256 thr (8 warps 2x4). All operands u32 tf32.
// 3-stage cp.async pipeline, ONE __syncthreads per K-step.
// Dynamic smem: A stages 3*3072 | B stages 3*2048 = 15360 u32 = 61440 B.
// Iter i: wait(group i) -> sync -> issue load stage (i+2)%3 [= stage consumed
// at i-1; safe: sync proves all warps finished i-1] -> consume stage i%3.
// ---------------------------------------------------------------------------
__device__ __forceinline__ void gemm_core(const unsigned* __restrict__ A,
                                          const unsigned* __restrict__ Wp,
                                          unsigned* sm,
                                          float acc[4][4][4],
                                          int rowBase, int colBase)
{
    const int tid  = threadIdx.x;
    const int wid  = tid >> 5;
    const int lane = tid & 31;
    const int g    = lane >> 2;
    const int t4   = lane & 3;
    const int wm   = wid >> 2;
    const int wn   = wid & 3;

    #pragma unroll
    for (int mt = 0; mt < 4; mt++)
        #pragma unroll
        for (int nt = 0; nt < 4; nt++)
            #pragma unroll
            for (int i = 0; i < 4; i++) acc[mt][nt][i] = 0.f;

    auto loadT = [&](int k0, int s) {
        unsigned* Ad = sm + s * 3072;
        unsigned* Bd = sm + 9216 + s * 2048;
        #pragma unroll
        for (int j = 0; j < 2; j++) {
            int c = tid + j * 256;                      // 0..511
            int ra = c >> 2, ch = c & 3;
            cpa16(&Ad[ra * 24 + ch * 4],
                  A + (size_t)(rowBase + ra) * DM + k0 + ch * 4);
            int ksl = c >> 8, rem = c & 255;
            int rb = rem >> 1, hc = rem & 1;
            cpa16(&Bd[ksl * 1024 + rb * 8 + hc * 4],
                  Wp + (size_t)((k0 >> 3) + ksl) * (NHD * 8) + (colBase + rb) * 8 + hc * 4);
        }
    };

    loadT(0, 0);  cp_commit();
    loadT(16, 1); cp_commit();
    int s_use = 0, s_load = 2;

    for (int k0 = 0; k0 < DM; k0 += 16) {
        if (k0 + 16 < DM) cp_wait<1>(); else cp_wait<0>();
        __syncthreads();
        if (k0 + 32 < DM) { loadT(k0 + 32, s_load); cp_commit(); }

        const unsigned* Ad = sm + s_use * 3072;
        const unsigned* Bd = sm + 9216 + s_use * 2048;

        #pragma unroll
        for (int ks = 0; ks < 2; ks++) {
            unsigned af[4][4], bf[4][2];
            #pragma unroll
            for (int mt = 0; mt < 4; mt++) {
                const int row = wm * 64 + mt * 16 + g;
                uint2 a01 = *(const uint2*)&Ad[row * 24 + ks * 8 + 2 * t4];
                uint2 a23 = *(const uint2*)&Ad[(row + 8) * 24 + ks * 8 + 2 * t4];
                af[mt][0] = a01.x; af[mt][1] = a23.x; af[mt][2] = a01.y; af[mt][3] = a23.y;
            }
            #pragma unroll
            for (int nt = 0; nt < 4; nt++) {
                uint2 bb = *(const uint2*)&Bd[ks * 1024 + (wn * 32 + nt * 8 + g) * 8 + 2 * t4];
                bf[nt][0] = bb.x; bf[nt][1] = bb.y;
            }
            #pragma unroll
            for (int mt = 0; mt < 4; mt++)
                #pragma unroll
                for (int nt = 0; nt < 4; nt++)
                    mma8(acc[mt][nt], af[mt], bf[nt][0], bf[nt][1]);
        }
        s_use  = (s_use  + 1) % 3;
        s_load = (s_load + 1) % 3;
    }
}

// merged QKV projection: grid.z = 0(Q)/1(K)/2(V)
__global__ void __launch_bounds__(256) qkv_gemm(
    const unsigned* __restrict__ xq, const unsigned* __restrict__ xk,
    const unsigned* __restrict__ xv, const unsigned* __restrict__ wq,
    const unsigned* __restrict__ wk, const unsigned* __restrict__ wv,
    unsigned* __restrict__ oq, unsigned* __restrict__ ok, unsigned* __restrict__ ov)
{
    extern __shared__ unsigned smd[];
    const int z = blockIdx.z;
    const unsigned* A  = (z == 0) ? xq : (z == 1) ? xk : xv;
    const unsigned* Wp = (z == 0) ? wq : (z == 1) ? wk : wv;

    const int rowBase = blockIdx.y * 128;
    const int colBase = blockIdx.x * 128;
    float acc[4][4][4];
    gemm_core(A, Wp, smd, acc, rowBase, colBase);

    const int tid = threadIdx.x, wid = tid >> 5, lane = tid & 31;
    const int g = lane >> 2, t4 = lane & 3, wm = wid >> 2, wn = wid & 3;
    const int pA = pos8(2 * t4), pB = pos8(2 * t4 + 1);

    if (z < 2) {   // Q or K: [b,h][s][d perm8]
        unsigned* O = z ? ok : oq;
        const float sc = z ? 1.f : 0.125f * LOG2E;
        #pragma unroll
        for (int mt = 0; mt < 4; mt++) {
            const int r0 = rowBase + wm * 64 + mt * 16 + g;
            const int bI = r0 >> 11, sI = r0 & 2047;
            #pragma unroll
            for (int nt = 0; nt < 4; nt++) {
                const int c0 = colBase + wn * 32 + nt * 8 + 2 * t4;
                const int hI = c0 >> 6, dg = (c0 & 63) & ~7;
                size_t b0 = ((size_t)(bI * NH + hI) * SS + sI) * DK + dg;
                size_t b1 = b0 + 8 * DK;
                O[b0 + pA] = f2tf(acc[mt][nt][0] * sc);
                O[b0 + pB] = f2tf(acc[mt][nt][1] * sc);
                O[b1 + pA] = f2tf(acc[mt][nt][2] * sc);
                O[b1 + pB] = f2tf(acc[mt][nt][3] * sc);
            }
        }
    } else {       // V transposed: [b,h][d][s perm8]
        const int pG = pos8(g);
        #pragma unroll
        for (int mt = 0; mt < 4; mt++) {
            const int r0 = rowBase + wm * 64 + mt * 16 + g;
            const int bI = r0 >> 11, sI = r0 & 2047;
            const int sp = (sI & ~7) + pG;
            #pragma unroll
            for (int nt = 0; nt < 4; nt++) {
                const int c0 = colBase + wn * 32 + nt * 8 + 2 * t4;
                const int hI = c0 >> 6, dI = c0 & 63;
                size_t base = ((size_t)(bI * NH + hI) * DK + dI) * SS;
                ov[base + sp]          = f2tf(acc[mt][nt][0]);
                ov[base + SS + sp]     = f2tf(acc[mt][nt][1]);
                ov[base + sp + 8]      = f2tf(acc[mt][nt][2]);
                ov[base + SS + sp + 8] = f2tf(acc[mt][nt][3]);
            }
        }
    }
}

__global__ void __launch_bounds__(256) out_gemm(const unsigned* __restrict__ ctx,
                                                const unsigned* __restrict__ wo,
                                                float* __restrict__ C)
{
    extern __shared__ unsigned smd[];
    const int rowBase = blockIdx.y * 128;
    const int colBase = blockIdx.x * 128;
    float acc[4][4][4];
    gemm_core(ctx, wo, smd, acc, rowBase, colBase);

    const int tid = threadIdx.x, wid = tid >> 5, lane = tid & 31;
    const int g = lane >> 2, t4 = lane & 3, wm = wid >> 2, wn = wid & 3;
    #pragma unroll
    for (int mt = 0; mt < 4; mt++) {
        const int r0 = rowBase + wm * 64 + mt * 16 + g;
        #pragma unroll
        for (int nt = 0; nt < 4; nt++) {
            const int c0 = colBase + wn * 32 + nt * 8 + 2 * t4;
            *(float2*)&C[(size_t)r0 * NHD + c0]       = make_float2(acc[mt][nt][0], acc[mt][nt][1]);
            *(float2*)&C[(size_t)(r0 + 8) * NHD + c0] = make_float2(acc[mt][nt][2], acc[mt][nt][3]);
        }
    }
}

// ---------------------------------------------------------------------------
// Tensor-core flash attention (R13 config: 128 thr, 2 CTAs/SM, 1024 blocks).
// grid (S/64, H, B), 4 warps, warp w owns q-rows [16w, 16w+16).
// smem u32: Ks[2][64*72] | Vt[2][64*72] | Ps[64*72]  = 92160 B
// ---------------------------------------------------------------------------
__global__ void __launch_bounds__(128) attn_tc2(const unsigned* __restrict__ q,
                                                const unsigned* __restrict__ k,
                                                const unsigned* __restrict__ v,
                                                const float* __restrict__ maskl,
                                                unsigned* __restrict__ ctx)
{
    extern __shared__ unsigned sm[];
    unsigned* Ks0 = sm;              // 2 * 4608
    unsigned* Vs0 = sm + 9216;       // 2 * 4608
    unsigned* Ps  = sm + 18432;      // 4608

    const int tid  = threadIdx.x;
    const int wid  = tid >> 5;
    const int lane = tid & 31;
    const int g    = lane >> 2;
    const int t4   = lane & 3;
    const int m0   = wid * 16;
    const int pA   = pos8(2 * t4), pB = pos8(2 * t4 + 1);

    const int bh = blockIdx.z * NH + blockIdx.y;
    const int q0 = blockIdx.x * 64;
    const unsigned* kb = k + (size_t)bh * SS * DK;
    const unsigned* vb = v + (size_t)bh * DK * SS;
    const float* mrow  = maskl + (size_t)blockIdx.z * SS;

    // Q fragments straight from gmem (prepped: tf32 bits, 0.125*log2e folded)
    unsigned qa[8][4];
    const unsigned* qp = q + ((size_t)bh * SS + q0 + m0 + g) * DK;
    #pragma unroll
    for (int ks = 0; ks < 8; ks++) {
        uint2 u0 = *(const uint2*)(qp + ks * 8 + 2 * t4);
        uint2 u1 = *(const uint2*)(qp + 8 * DK + ks * 8 + 2 * t4);
        qa[ks][0] = u0.x; qa[ks][1] = u1.x; qa[ks][2] = u0.y; qa[ks][3] = u1.y;
    }

    auto loadKV = [&](int kv0, int bufi) {
        unsigned* Kd = Ks0 + bufi * 4608;
        unsigned* Vd = Vs0 + bufi * 4608;
        #pragma unroll
        for (int j = 0; j < 8; j++) {
            int idx = tid + j * 128;          // 0..1023
            int r = idx >> 4, c = idx & 15;   // row, 16B chunk
            cpa16(&Kd[r * 72 + c * 4], kb + (size_t)(kv0 + r) * DK + c * 4);
            cpa16(&Vd[r * 72 + c * 4], vb + (size_t)r * SS + kv0 + c * 4);
        }
    };

    float o[8][4];
    #pragma unroll
    for (int nt = 0; nt < 8; nt++)
        #pragma unroll
        for (int i = 0; i < 4; i++) o[nt][i] = 0.f;
    float l0 = 0.f, l1 = 0.f;

    loadKV(0, 0); cp_commit();
    int buf = 0;

    for (int it = 0; it < SS / 64; it++) {
        const int kv0 = it * 64;
        if (it + 1 < SS / 64) { loadKV(kv0 + 64, buf ^ 1); cp_commit(); cp_wait<1>(); }
        else                  { cp_wait<0>(); }
        __syncthreads();

        const unsigned* Ks = Ks0 + buf * 4608;
        const unsigned* Vs = Vs0 + buf * 4608;

        // ---- scores (log2e-scaled): S = Q @ K^T ----
        float s[8][4];
        #pragma unroll
        for (int nt = 0; nt < 8; nt++)
            #pragma unroll
            for (int i = 0; i < 4; i++) s[nt][i] = 0.f;

        #pragma unroll
        for (int ks = 0; ks < 8; ks++) {
            #pragma unroll
            for (int nt = 0; nt < 8; nt++) {
                uint2 kk2 = *(const uint2*)&Ks[(nt * 8 + g) * 72 + ks * 8 + 2 * t4];
                mma8(s[nt], qa[ks], kk2.x, kk2.y);
            }
        }

        // ---- p = 2^(s + mask*log2e); row sums; P -> smem ----
        #pragma unroll
        for (int nt = 0; nt < 8; nt++) {
            const int c = nt * 8 + 2 * t4;
            const float mk0 = __ldg(&mrow[kv0 + c]);
            const float mk1 = __ldg(&mrow[kv0 + c + 1]);
            float p0 = fex2(s[nt][0] + mk0);
            float p1 = fex2(s[nt][1] + mk1);
            float p2 = fex2(s[nt][2] + mk0);
            float p3 = fex2(s[nt][3] + mk1);
            l0 += p0 + p1;
            l1 += p2 + p3;
            const int base = (m0 + g) * 72 + nt * 8;
            Ps[base + pA]          = f2tf(p0);
            Ps[base + pB]          = f2tf(p1);
            Ps[base + 8 * 72 + pA] = f2tf(p2);
            Ps[base + 8 * 72 + pB] = f2tf(p3);
        }
        __syncwarp();   // P rows are private to this warp

        // ---- O += P @ V ----
        #pragma unroll
        for (int ks = 0; ks < 8; ks++) {
            uint2 pa01 = *(const uint2*)&Ps[(m0 + g) * 72 + ks * 8 + 2 * t4];
            uint2 pa23 = *(const uint2*)&Ps[(m0 + 8 + g) * 72 + ks * 8 + 2 * t4];
            unsigned pa[4] = { pa01.x, pa23.x, pa01.y, pa23.y };
            #pragma unroll
            for (int nt = 0; nt < 8; nt++) {
                uint2 vv = *(const uint2*)&Vs[(nt * 8 + g) * 72 + ks * 8 + 2 * t4];
                mma8(o[nt], pa, vv.x, vv.y);
            }
        }
        __syncthreads();   // everyone done with buf before refill
        buf ^= 1;
    }

    // ---- deferred row-sum reduction + normalize + write prepped ctx ----
    l0 += __shfl_xor_sync(0xffffffffu, l0, 1);
    l0 += __shfl_xor_sync(0xffffffffu, l0, 2);
    l1 += __shfl_xor_sync(0xffffffffu, l1, 1);
    l1 += __shfl_xor_sync(0xffffffffu, l1, 2);
    const float inv0 = 1.f / l0;
    const float inv1 = 1.f / l1;

    const int row0 = q0 + m0 + g;
    const size_t ob = ((size_t)blockIdx.z * SS + row0) * NHD + blockIdx.y * DK;
    #pragma unroll
    for (int nt = 0; nt < 8; nt++) {
        const size_t cb = ob + nt * 8;
        ctx[cb + pA]           = f2tf(o[nt][0] * inv0);
        ctx[cb + pB]           = f2tf(o[nt][1] * inv0);
        ctx[cb + 8 * NHD + pA] = f2tf(o[nt][2] * inv1);
        ctx[cb + 8 * NHD + pB] = f2tf(o[nt][3] * inv1);
    }
}

// ---------------------------------------------------------------------------
// Launch
// ---------------------------------------------------------------------------
extern "C" void kernel_launch(void* const* d_in, const int* in_sizes, int n_in,
                              void* d_out, int out_size)
{
    (void)in_sizes; (void)n_in; (void)out_size;
    const float* query = (const float*)d_in[0];
    const float* key   = (const float*)d_in[1];
    const float* value = (const float*)d_in[2];
    const float* mask  = (const float*)d_in[3];
    const float* Wq    = (const float*)d_in[4];
    const float* Wk    = (const float*)d_in[5];
    const float* Wv    = (const float*)d_in[6];
    const float* Wo    = (const float*)d_in[7];
    float* out = (float*)d_out;

    unsigned *xq, *xk, *xv, *wq, *wk, *wv, *wo, *qd, *kd, *vd, *ctx;
    float* ml;
    cudaGetSymbolAddress((void**)&xq,  g_xq);
    cudaGetSymbolAddress((void**)&xk,  g_xk);
    cudaGetSymbolAddress((void**)&xv,  g_xv);
    cudaGetSymbolAddress((void**)&wq,  g_wq);
    cudaGetSymbolAddress((void**)&wk,  g_wk);
    cudaGetSymbolAddress((void**)&wv,  g_wv);
    cudaGetSymbolAddress((void**)&wo,  g_wo);
    cudaGetSymbolAddress((void**)&qd,  g_q);
    cudaGetSymbolAddress((void**)&kd,  g_k);
    cudaGetSymbolAddress((void**)&vd,  g_v);
    cudaGetSymbolAddress((void**)&ctx, g_ctx);
    cudaGetSymbolAddress((void**)&ml,  g_maskl);

    const int gemm_smem = 15360 * 4;     // 61440 B (3-stage pipeline)
    const int attn_smem = 23040 * 4;     // 92160 B
    static int attr_set = 0;
    if (!attr_set) {
        cudaFuncSetAttribute(qkv_gemm, cudaFuncAttributeMaxDynamicSharedMemorySize, gemm_smem);
        cudaFuncSetAttribute(out_gemm, cudaFuncAttributeMaxDynamicSharedMemorySize, gemm_smem);
        cudaFuncSetAttribute(attn_tc2, cudaFuncAttributeMaxDynamicSharedMemorySize, attn_smem);
        attr_set = 1;
    }

    // preps (merged)
    prep_x3<<<dim3(2048, 3), 256>>>(query, key, value, xq, xk, xv);
    prep_w4<<<dim3(512, 4), 256>>>(Wq, Wk, Wv, Wo, wq, wk, wv, wo);
    prep_mask<<<16, 256>>>(mask, ml);

    // merged QKV projection
    dim3 qgrid(NHD / 128, MTOT / 128, 3);   // (8, 32, 3)
    qkv_gemm<<<qgrid, 256, gemm_smem>>>(xq, xk, xv, wq, wk, wv, qd, kd, vd);

    // attention
    dim3 agrid(SS / 64, NH, BB);            // (32, 16, 2)
    attn_tc2<<<agrid, 128, attn_smem>>>(qd, kd, vd, ml, ctx);

    // output projection
    dim3 ogrid(NHD / 128, MTOT / 128);      // (8, 32)
    out_gemm<<<ogrid, 256, gemm_smem>>>(ctx, wo, out);
}

// round 16
// speedup vs baseline: 1.5805x; 1.0585x over previous
#include <cuda_runtime.h>

// Problem constants
#define BB 2
#define SS 2048
#define DM 1024
#define NH 16
#define DK 64
#define MTOT (BB*SS)      // 4096
#define NHD  (NH*DK)      // 1024
#define LOG2E 1.44269504088896f

// Scratch (allocation-free static device globals). u32 = tf32 bit payloads.
// Fragment-native layouts ("A-layout"): [rowblk16][k8][lane32][4slots]
//   slot x=(row g,  k t4), y=(g+8, t4), z=(g, t4+4), w=(g+8, t4+4); lane=g*4+t4.
__device__ unsigned g_xq[MTOT*DM];     // activations, A-layout over [MTOT][DM]
__device__ unsigned g_xk[MTOT*DM];
__device__ unsigned g_xv[MTOT*DM];
__device__ unsigned g_wq[DM*NHD];      // weights, B-layout [a=k8 128][nblk16 64][lane][4]
__device__ unsigned g_wk[DM*NHD];
__device__ unsigned g_wv[DM*NHD];
__device__ unsigned g_wo[NHD*DM];
__device__ unsigned g_q[BB*NH*SS*DK];  // per bh: A-layout [sblk 128][k8 8][lane][4] (x0.125*log2e)
__device__ unsigned g_k[BB*NH*SS*DK];  // per bh: same layout as g_q
__device__ unsigned g_v[BB*NH*DK*SS];  // per bh: [dblk16 4][kv8 256][lane][4]
__device__ unsigned g_ctx[MTOT*NHD];   // A-layout over [MTOT][NHD]
__device__ float    g_maskl[BB*SS];    // mask * log2e

// ---------------------------------------------------------------------------
// helpers
// ---------------------------------------------------------------------------
__device__ __forceinline__ unsigned f2tf(float x) {
    unsigned u; asm("cvt.rna.tf32.f32 %0, %1;" : "=r"(u) : "f"(x)); return u;
}
__device__ __forceinline__ float fex2(float x) {
    float y; asm("ex2.approx.ftz.f32 %0, %1;" : "=f"(y) : "f"(x)); return y;
}
__device__ __forceinline__ void mma8(float* c, const unsigned* a, unsigned b0, unsigned b1) {
    asm volatile(
        "mma.sync.aligned.m16n8k8.row.col.f32.tf32.tf32.f32 "
        "{%0,%1,%2,%3}, {%4,%5,%6,%7}, {%8,%9}, {%0,%1,%2,%3};\n"
        : "+f"(c[0]), "+f"(c[1]), "+f"(c[2]), "+f"(c[3])
        : "r"(a[0]), "r"(a[1]), "r"(a[2]), "r"(a[3]), "r"(b0), "r"(b1));
}
__device__ __forceinline__ void cpa16(void* dst, const void* src) {
    unsigned d = (unsigned)__cvta_generic_to_shared(dst);
    asm volatile("cp.async.cg.shared.global [%0], [%1], 16;\n" :: "r"(d), "l"(src));
}
__device__ __forceinline__ void cp_commit() { asm volatile("cp.async.commit_group;\n"); }
template <int N>
__device__ __forceinline__ void cp_wait() { asm volatile("cp.async.wait_group %0;\n" :: "n"(N)); }

// pairing permutation for the P smem buffer only
__device__ __forceinline__ int pos8(int j) { return (j & 3) * 2 + (j >> 2); }

// A-layout address (u32 units) within a [nrowblk][nk8] region: row r, col k
__device__ __forceinline__ int aidx(int r, int k, int nk8) {
    return (r >> 4) * (nk8 * 128) + ((k >> 3) % nk8) * 128
         + ((r & 7) * 4 + (k & 3)) * 4 + ((k >> 2) & 1) * 2 + ((r >> 3) & 1);
}

// ---------------------------------------------------------------------------
// prep kernels: write fragment-native layouts
// ---------------------------------------------------------------------------
// activations -> A-layout [Rblk 256][k8 128][lane][4]
__global__ void __launch_bounds__(256) prep_x3(const float* __restrict__ Xq,
                                               const float* __restrict__ Xk,
                                               const float* __restrict__ Xv,
                                               unsigned* __restrict__ Pq,
                                               unsigned* __restrict__ Pk,
                                               unsigned* __restrict__ Pv)
{
    const int z = blockIdx.y;
    const float* X = (z == 0) ? Xq : (z == 1) ? Xk : Xv;
    unsigned* Xp   = (z == 0) ? Pq : (z == 1) ? Pk : Pv;
    int id = blockIdx.x * 256 + threadIdx.x;   // 1048576 = 256blk * 128k8 * 32lane
    int blk = id >> 12, k8 = (id >> 5) & 127, lane = id & 31;
    int g = lane >> 2, t4 = lane & 3;
    int r0 = blk * 16 + g, k0 = k8 * 8 + t4;
    uint4 o;
    o.x = f2tf(X[(size_t)r0 * DM + k0]);
    o.y = f2tf(X[(size_t)(r0 + 8) * DM + k0]);
    o.z = f2tf(X[(size_t)r0 * DM + k0 + 4]);
    o.w = f2tf(X[(size_t)(r0 + 8) * DM + k0 + 4]);
    *(uint4*)(Xp + (size_t)id * 4) = o;
}

// weights [k 1024][n 1024] -> B-layout [a=k8 128][nblk 64][lane][4]
// slots: x=(n nblk*16+g, k 8a+t4), y=(n +8, k t4), z=(n g, k t4+4), w=(n +8, k t4+4)
__global__ void __launch_bounds__(256) prep_w4(const float* __restrict__ Wq,
                                               const float* __restrict__ Wk,
                                               const float* __restrict__ Wv,
                                               const float* __restrict__ Wo,
                                               unsigned* __restrict__ Pq,
                                               unsigned* __restrict__ Pk,
                                               unsigned* __restrict__ Pv,
                                               unsigned* __restrict__ Po)
{
    const int z = blockIdx.y;
    const float* W = (z == 0) ? Wq : (z == 1) ? Wk : (z == 2) ? Wv : Wo;
    unsigned* Wp   = (z == 0) ? Pq : (z == 1) ? Pk : (z == 2) ? Pv : Po;
    int id = blockIdx.x * 256 + threadIdx.x;   // 262144 = 128a * 64nblk * 32lane
    int a = id >> 11, nblk = (id >> 5) & 63, lane = id & 31;
    int g = lane >> 2, t4 = lane & 3;
    int n0 = nblk * 16 + g, k0 = 8 * a + t4;
    uint4 o;
    o.x = f2tf(W[(size_t)k0 * NHD + n0]);
    o.y = f2tf(W[(size_t)k0 * NHD + n0 + 8]);
    o.z = f2tf(W[(size_t)(k0 + 4) * NHD + n0]);
    o.w = f2tf(W[(size_t)(k0 + 4) * NHD + n0 + 8]);
    *(uint4*)(Wp + (size_t)id * 4) = o;
}

__global__ void __launch_bounds__(256) prep_mask(const float* __restrict__ m,
                                                 float* __restrict__ out)
{
    int id = blockIdx.x * 256 + threadIdx.x;   // 4096
    out[id] = m[id] * LOG2E;
}

// ---------------------------------------------------------------------------
// GEMM core: 128x128 tile, BK=16, 256 thr (8 warps 2x4). Fragment-native smem:
// A stage [rowblk 8][k8 2][lane][4] = 2048 u32; B stage [a 2][nblk 8][lane][4] = 2048.
// 3 stages each => 12288 u32 = 49152 B dynamic. One LDS.128 per fragment(-pair).
// ---------------------------------------------------------------------------
__device__ __forceinline__ void gemm_core(const unsigned* __restrict__ A,
                                          const unsigned* __restrict__ Wp,
                                          unsigned* sm,
                                          float acc[4][4][4],
                                          int rowBase, int colBase)
{
    const int tid  = threadIdx.x;
    const int wid  = tid >> 5;
    const int lane = tid & 31;
    const int wm   = wid >> 2;
    const int wn   = wid & 3;

    #pragma unroll
    for (int mt = 0; mt < 4; mt++)
        #pragma unroll
        for (int nt = 0; nt < 4; nt++)
            #pragma unroll
            for (int i = 0; i < 4; i++) acc[mt][nt][i] = 0.f;

    auto loadT = [&](int k0, int s) {
        unsigned* Ad = sm + s * 2048;
        unsigned* Bd = sm + 6144 + s * 2048;
        #pragma unroll
        for (int j = 0; j < 2; j++) {
            int c = tid + j * 256;                      // 0..511 chunks of 16B
            cpa16(&Ad[c * 4],
                  A + (size_t)((rowBase >> 4) + (c >> 6)) * 16384
                    + ((k0 >> 3) + ((c >> 5) & 1)) * 128 + (c & 31) * 4);
            cpa16(&Bd[c * 4],
                  Wp + (size_t)((k0 >> 3) + (c >> 8)) * 8192
                     + ((colBase >> 4) + ((c >> 5) & 7)) * 128 + (c & 31) * 4);
        }
    };

    loadT(0, 0);  cp_commit();
    loadT(16, 1); cp_commit();
    int s_use = 0, s_load = 2;

    for (int k0 = 0; k0 < DM; k0 += 16) {
        if (k0 + 16 < DM) cp_wait<1>(); else cp_wait<0>();
        __syncthreads();
        if (k0 + 32 < DM) { loadT(k0 + 32, s_load); cp_commit(); }

        const unsigned* Ad = sm + s_use * 2048;
        const unsigned* Bd = sm + 6144 + s_use * 2048;

        #pragma unroll
        for (int ks = 0; ks < 2; ks++) {
            unsigned af[4][4];
            #pragma unroll
            for (int mt = 0; mt < 4; mt++) {
                uint4 u = *(const uint4*)&Ad[(wm * 4 + mt) * 256 + ks * 128 + lane * 4];
                af[mt][0] = u.x; af[mt][1] = u.y; af[mt][2] = u.z; af[mt][3] = u.w;
            }
            #pragma unroll
            for (int p = 0; p < 2; p++) {
                uint4 b = *(const uint4*)&Bd[ks * 1024 + (wn * 2 + p) * 128 + lane * 4];
                #pragma unroll
                for (int mt = 0; mt < 4; mt++) {
                    mma8(acc[mt][2 * p],     af[mt], b.x, b.z);
                    mma8(acc[mt][2 * p + 1], af[mt], b.y, b.w);
                }
            }
        }
        s_use  = (s_use  + 1) % 3;
        s_load = (s_load + 1) % 3;
    }
}

// merged QKV projection: grid.z = 0(Q)/1(K)/2(V)
__global__ void __launch_bounds__(256) qkv_gemm(
    const unsigned* __restrict__ xq, const unsigned* __restrict__ xk,
    const unsigned* __restrict__ xv, const unsigned* __restrict__ wq,
    const unsigned* __restrict__ wk, const unsigned* __restrict__ wv,
    unsigned* __restrict__ oq, unsigned* __restrict__ ok, unsigned* __restrict__ ov)
{
    extern __shared__ unsigned smd[];
    const int z = blockIdx.z;
    const unsigned* A  = (z == 0) ? xq : (z == 1) ? xk : xv;
    const unsigned* Wp = (z == 0) ? wq : (z == 1) ? wk : wv;

    const int rowBase = blockIdx.y * 128;
    const int colBase = blockIdx.x * 128;
    float acc[4][4][4];
    gemm_core(A, Wp, smd, acc, rowBase, colBase);

    const int tid = threadIdx.x, wid = tid >> 5, lane = tid & 31;
    const int g = lane >> 2, t4 = lane & 3, wm = wid >> 2, wn = wid & 3;

    if (z < 2) {   // Q or K -> per-bh A-layout [sblk 128][k8 8][lane][4]
        unsigned* O = z ? ok : oq;
        const float sc = z ? 1.f : 0.125f * LOG2E;
        #pragma unroll
        for (int mt = 0; mt < 4; mt++) {
            const int rA = rowBase + wm * 64 + mt * 16 + g;
            const int bI = rA >> 11, sI = rA & 2047;
            #pragma unroll
            for (int nt = 0; nt < 4; nt++) {
                const int c0 = colBase + wn * 32 + nt * 8 + 2 * t4;
                const int hI = c0 >> 6, d0 = c0 & 63;
                unsigned* base = O + (size_t)(bI * NH + hI) * 131072;
                base[aidx(sI,     d0,     8)] = f2tf(acc[mt][nt][0] * sc);
                base[aidx(sI,     d0 + 1, 8)] = f2tf(acc[mt][nt][1] * sc);
                base[aidx(sI + 8, d0,     8)] = f2tf(acc[mt][nt][2] * sc);
                base[aidx(sI + 8, d0 + 1, 8)] = f2tf(acc[mt][nt][3] * sc);
            }
        }
    } else {       // V -> per-bh B-layout [dblk16 4][kv8 256][lane][4]
        #pragma unroll
        for (int mt = 0; mt < 4; mt++) {
            const int rA = rowBase + wm * 64 + mt * 16 + g;
            const int bI = rA >> 11, sI = rA & 2047;
            #pragma unroll
            for (int nt = 0; nt < 4; nt++) {
                const int c0 = colBase + wn * 32 + nt * 8 + 2 * t4;
                const int hI = c0 >> 6, d0 = c0 & 63;
                unsigned* base = ov + (size_t)(bI * NH + hI) * 131072;
                auto vdx = [](int s, int d) {
                    return (d >> 4) * 32768 + (s >> 3) * 128
                         + ((d & 7) * 4 + (s & 3)) * 4 + ((s >> 2) & 1) * 2 + ((d >> 3) & 1);
                };
                base[vdx(sI,     d0    )] = f2tf(acc[mt][nt][0]);
                base[vdx(sI,     d0 + 1)] = f2tf(acc[mt][nt][1]);
                base[vdx(sI + 8, d0    )] = f2tf(acc[mt][nt][2]);
                base[vdx(sI + 8, d0 + 1)] = f2tf(acc[mt][nt][3]);
            }
        }
    }
}

__global__ void __launch_bounds__(256) out_gemm(const unsigned* __restrict__ ctx,
                                                const unsigned* __restrict__ wo,
                                                float* __restrict__ C)
{
    extern __shared__ unsigned smd[];
    const int rowBase = blockIdx.y * 128;
    const int colBase = blockIdx.x * 128;
    float acc[4][4][4];
    gemm_core(ctx, wo, smd, acc, rowBase, colBase);

    const int tid = threadIdx.x, wid = tid >> 5, lane = tid & 31;
    const int g = lane >> 2, t4 = lane & 3, wm = wid >> 2, wn = wid & 3;
    #pragma unroll
    for (int mt = 0; mt < 4; mt++) {
        const int r0 = rowBase + wm * 64 + mt * 16 + g;
        #pragma unroll
        for (int nt = 0; nt < 4; nt++) {
            const int c0 = colBase + wn * 32 + nt * 8 + 2 * t4;
            *(float2*)&C[(size_t)r0 * NHD + c0]       = make_float2(acc[mt][nt][0], acc[mt][nt][1]);
            *(float2*)&C[(size_t)(r0 + 8) * NHD + c0] = make_float2(acc[mt][nt][2], acc[mt][nt][3]);
        }
    }
}

// ---------------------------------------------------------------------------
// Tensor-core flash attention: 128 thr / 4 warps / 64 q-rows / 1024 blocks.
// K/V/Q fragments are single LDS.128/LDG.128 from fragment-native layouts.
// smem u32: Ks[2][4096] | Vs[2][4096] | Ps[64*72] = 20992 u32 = 83968 B.
// ---------------------------------------------------------------------------
__global__ void __launch_bounds__(128) attn_tc2(const unsigned* __restrict__ q,
                                                const unsigned* __restrict__ k,
                                                const unsigned* __restrict__ v,
                                                const float* __restrict__ maskl,
                                                unsigned* __restrict__ ctx)
{
    extern __shared__ unsigned sm[];
    unsigned* Ks0 = sm;              // 2 * 4096  [kvblk 4][k8 8][lane][4]
    unsigned* Vs0 = sm + 8192;       // 2 * 4096  [dblk 4][kv8 8][lane][4]
    unsigned* Ps  = sm + 16384;      // 64*72

    const int tid  = threadIdx.x;
    const int wid  = tid >> 5;
    const int lane = tid & 31;
    const int g    = lane >> 2;
    const int t4   = lane & 3;
    const int m0   = wid * 16;
    const int pA   = pos8(2 * t4), pB = pos8(2 * t4 + 1);

    const int bh = blockIdx.z * NH + blockIdx.y;
    const int q0 = blockIdx.x * 64;
    const unsigned* kb = k + (size_t)bh * 131072;
    const unsigned* vb = v + (size_t)bh * 131072;
    const float* mrow  = maskl + (size_t)blockIdx.z * SS;

    // Q fragments: one LDG.128 per ks
    unsigned qa[8][4];
    {
        const unsigned* qp = q + (size_t)bh * 131072 + ((q0 + m0) >> 4) * 1024 + lane * 4;
        #pragma unroll
        for (int ks = 0; ks < 8; ks++) {
            uint4 u = *(const uint4*)(qp + ks * 128);
            qa[ks][0] = u.x; qa[ks][1] = u.y; qa[ks][2] = u.z; qa[ks][3] = u.w;
        }
    }

    auto loadKV = [&](int kv0, int bufi) {
        unsigned* Kd = Ks0 + bufi * 4096;
        unsigned* Vd = Vs0 + bufi * 4096;
        const unsigned* ksrc = kb + (kv0 >> 4) * 1024;           // contiguous 4096 u32
        #pragma unroll
        for (int j = 0; j < 8; j++) {
            int idx = tid + j * 128;          // 0..1023 chunks of 16B
            cpa16(&Kd[idx * 4], ksrc + idx * 4);
            cpa16(&Vd[idx * 4], vb + (idx >> 8) * 32768 + (kv0 << 4) + (idx & 255) * 4);
        }
    };

    float o[8][4];
    #pragma unroll
    for (int nt = 0; nt < 8; nt++)
        #pragma unroll
        for (int i = 0; i < 4; i++) o[nt][i] = 0.f;
    float l0 = 0.f, l1 = 0.f;

    loadKV(0, 0); cp_commit();
    int buf = 0;

    for (int it = 0; it < SS / 64; it++) {
        const int kv0 = it * 64;
        if (it + 1 < SS / 64) { loadKV(kv0 + 64, buf ^ 1); cp_commit(); cp_wait<1>(); }
        else                  { cp_wait<0>(); }
        __syncthreads();

        const unsigned* Ks = Ks0 + buf * 4096;
        const unsigned* Vs = Vs0 + buf * 4096;

        // ---- scores (log2e-scaled): S = Q @ K^T ----
        float s[8][4];
        #pragma unroll
        for (int nt = 0; nt < 8; nt++)
            #pragma unroll
            for (int i = 0; i < 4; i++) s[nt][i] = 0.f;

        #pragma unroll
        for (int ks = 0; ks < 8; ks++) {
            #pragma unroll
            for (int p = 0; p < 4; p++) {
                uint4 kk = *(const uint4*)&Ks[p * 1024 + ks * 128 + lane * 4];
                mma8(s[2 * p],     qa[ks], kk.x, kk.z);
                mma8(s[2 * p + 1], qa[ks], kk.y, kk.w);
            }
        }

        // ---- p = 2^(s + mask*log2e); row sums; P -> smem ----
        #pragma unroll
        for (int nt = 0; nt < 8; nt++) {
            const int c = nt * 8 + 2 * t4;
            const float mk0 = __ldg(&mrow[kv0 + c]);
            const float mk1 = __ldg(&mrow[kv0 + c + 1]);
            float p0 = fex2(s[nt][0] + mk0);
            float p1 = fex2(s[nt][1] + mk1);
            float p2 = fex2(s[nt][2] + mk0);
            float p3 = fex2(s[nt][3] + mk1);
            l0 += p0 + p1;
            l1 += p2 + p3;
            const int base = (m0 + g) * 72 + nt * 8;
            Ps[base + pA]          = f2tf(p0);
            Ps[base + pB]          = f2tf(p1);
            Ps[base + 8 * 72 + pA] = f2tf(p2);
            Ps[base + 8 * 72 + pB] = f2tf(p3);
        }
        __syncwarp();   // P rows are private to this warp

        // ---- O += P @ V ----
        #pragma unroll
        for (int ks = 0; ks < 8; ks++) {
            uint2 pa01 = *(const uint2*)&Ps[(m0 + g) * 72 + ks * 8 + 2 * t4];
            uint2 pa23 = *(const uint2*)&Ps[(m0 + 8 + g) * 72 + ks * 8 + 2 * t4];
            unsigned pa[4] = { pa01.x, pa23.x, pa01.y, pa23.y };
            #pragma unroll
            for (int p = 0; p < 4; p++) {
                uint4 vv = *(const uint4*)&Vs[p * 1024 + ks * 128 + lane * 4];
                mma8(o[2 * p],     pa, vv.x, vv.z);
                mma8(o[2 * p + 1], pa, vv.y, vv.w);
            }
        }
        __syncthreads();   // everyone done with buf before refill
        buf ^= 1;
    }

    // ---- deferred row-sum reduction + normalize + write ctx (A-layout) ----
    l0 += __shfl_xor_sync(0xffffffffu, l0, 1);
    l0 += __shfl_xor_sync(0xffffffffu, l0, 2);
    l1 += __shfl_xor_sync(0xffffffffu, l1, 1);
    l1 += __shfl_xor_sync(0xffffffffu, l1, 2);
    const float inv0 = 1.f / l0;
    const float inv1 = 1.f / l1;

    const int R0 = blockIdx.z * SS + q0 + m0 + g;
    #pragma unroll
    for (int nt = 0; nt < 8; nt++) {
        const int c = blockIdx.y * DK + nt * 8 + 2 * t4;
        ctx[(size_t)(R0 >> 4) * 16384 + aidx(R0 & 15,       c,     128)] = f2tf(o[nt][0] * inv0);
        ctx[(size_t)(R0 >> 4) * 16384 + aidx(R0 & 15,       c + 1, 128)] = f2tf(o[nt][1] * inv0);
        ctx[(size_t)(R0 >> 4) * 16384 + aidx((R0 & 15) + 8, c,     128)] = f2tf(o[nt][2] * inv1);
        ctx[(size_t)(R0 >> 4) * 16384 + aidx((R0 & 15) + 8, c + 1, 128)] = f2tf(o[nt][3] * inv1);
    }
}

// ---------------------------------------------------------------------------
// Launch
// ---------------------------------------------------------------------------
extern "C" void kernel_launch(void* const* d_in, const int* in_sizes, int n_in,
                              void* d_out, int out_size)
{
    (void)in_sizes; (void)n_in; (void)out_size;
    const float* query = (const float*)d_in[0];
    const float* key   = (const float*)d_in[1];
    const float* value = (const float*)d_in[2];
    const float* mask  = (const float*)d_in[3];
    const float* Wq    = (const float*)d_in[4];
    const float* Wk    = (const float*)d_in[5];
    const float* Wv    = (const float*)d_in[6];
    const float* Wo    = (const float*)d_in[7];
    float* out = (float*)d_out;

    unsigned *xq, *xk, *xv, *wq, *wk, *wv, *wo, *qd, *kd, *vd, *ctx;
    float* ml;
    cudaGetSymbolAddress((void**)&xq,  g_xq);
    cudaGetSymbolAddress((void**)&xk,  g_xk);
    cudaGetSymbolAddress((void**)&xv,  g_xv);
    cudaGetSymbolAddress((void**)&wq,  g_wq);
    cudaGetSymbolAddress((void**)&wk,  g_wk);
    cudaGetSymbolAddress((void**)&wv,  g_wv);
    cudaGetSymbolAddress((void**)&wo,  g_wo);
    cudaGetSymbolAddress((void**)&qd,  g_q);
    cudaGetSymbolAddress((void**)&kd,  g_k);
    cudaGetSymbolAddress((void**)&vd,  g_v);
    cudaGetSymbolAddress((void**)&ctx, g_ctx);
    cudaGetSymbolAddress((void**)&ml,  g_maskl);

    const int gemm_smem = 12288 * 4;     // 49152 B (3-stage, fragment-native)
    const int attn_smem = 20992 * 4;     // 83968 B
    static int attr_set = 0;
    if (!attr_set) {
        cudaFuncSetAttribute(qkv_gemm, cudaFuncAttributeMaxDynamicSharedMemorySize, gemm_smem);
        cudaFuncSetAttribute(out_gemm, cudaFuncAttributeMaxDynamicSharedMemorySize, gemm_smem);
        cudaFuncSetAttribute(attn_tc2, cudaFuncAttributeMaxDynamicSharedMemorySize, attn_smem);
        attr_set = 1;
    }

    // preps (fragment-native layouts)
    prep_x3<<<dim3(4096, 3), 256>>>(query, key, value, xq, xk, xv);
    prep_w4<<<dim3(1024, 4), 256>>>(Wq, Wk, Wv, Wo, wq, wk, wv, wo);
    prep_mask<<<16, 256>>>(mask, ml);

    // merged QKV projection
    dim3 qgrid(NHD / 128, MTOT / 128, 3);   // (8, 32, 3)
    qkv_gemm<<<qgrid, 256, gemm_smem>>>(xq, xk, xv, wq, wk, wv, qd, kd, vd);

    // attention
    dim3 agrid(SS / 64, NH, BB);            // (32, 16, 2)
    attn_tc2<<<agrid, 128, attn_smem>>>(qd, kd, vd, ml, ctx);

    // output projection
    dim3 ogrid(NHD / 128, MTOT / 128);      // (8, 32)
    out_gemm<<<ogrid, 256, gemm_smem>>>(ctx, wo, out);
}